// round 3
// baseline (speedup 1.0000x reference)
#include <cuda_runtime.h>
#include <cuda_fp16.h>
#include <cstdint>
#include <cstddef>

// ---------------------------------------------------------------------------
// Problem dims
// ---------------------------------------------------------------------------
#define BATCH_N 4096
#define DDIM    4096   // input(2048) + hidden(2048)
#define HDIM    2048

// GEMM tile: 256 (M) x 128 (N = 4 gates x 32 h-cols), BK = 64.
#define BM      256
#define BN      128
#define BK      64
#define NCHUNK  (DDIM / BK)                 // 64
#define NST     3
#define STAGE   49152                        // A 32KB + B 16KB
#define BOFF    32768                        // B tile offset within a stage
#define SOFF    1024                         // stages start (bias in [0,512))
#define SMEM_TOTAL (SOFF + NST * STAGE)      // 148480

// Staged fp16 operands (device globals: no allocation anywhere)
__device__ __align__(16) __half g_A[(size_t)BATCH_N * DDIM];   // 32 MB
__device__ __align__(16) __half g_W[(size_t)4 * HDIM * DDIM];  // 64 MB

// ---------------------------------------------------------------------------
// PTX helpers (all legal at compute_103 base target)
// ---------------------------------------------------------------------------
#define CP_ASYNC16(saddr, gptr) \
    asm volatile("cp.async.cg.shared.global [%0], [%1], 16;" \
                 :: "r"(saddr), "l"(gptr) : "memory")
#define CP_COMMIT() asm volatile("cp.async.commit_group;" ::: "memory")
#define CP_WAIT1()  asm volatile("cp.async.wait_group 1;"  ::: "memory")

#define LDSM_X4(r, addr)                                                      \
    asm volatile("ldmatrix.sync.aligned.m8n8.x4.shared.b16 {%0,%1,%2,%3}, [%4];" \
                 : "=r"((r)[0]), "=r"((r)[1]), "=r"((r)[2]), "=r"((r)[3])      \
                 : "r"(addr))

#define MMA16816(d, a, b0, b1)                                                \
    asm volatile(                                                             \
        "mma.sync.aligned.m16n8k16.row.col.f32.f16.f16.f32 "                  \
        "{%0,%1,%2,%3}, {%4,%5,%6,%7}, {%8,%9}, {%0,%1,%2,%3};"               \
        : "+f"((d)[0]), "+f"((d)[1]), "+f"((d)[2]), "+f"((d)[3])              \
        : "r"((a)[0]), "r"((a)[1]), "r"((a)[2]), "r"((a)[3]),                 \
          "r"(b0), "r"(b1))

__device__ __forceinline__ uint32_t smem_u32(const void* p) {
    return (uint32_t)__cvta_generic_to_shared(p);
}

// ---------------------------------------------------------------------------
// fp32 -> fp16 staging kernels
// ---------------------------------------------------------------------------
__device__ __forceinline__ uint32_t pack_h2(float lo, float hi) {
    __half2 t = __floats2half2_rn(lo, hi);  // .x = lower address
    return *reinterpret_cast<uint32_t*>(&t);
}

__global__ __launch_bounds__(256) void conv_a_kernel(
    const float* __restrict__ x, const float* __restrict__ h) {
    uint32_t v = blockIdx.x * 256u + threadIdx.x;   // 2,097,152 vec8
    uint32_t m  = v >> 9;
    uint32_t k8 = (v & 511u) << 3;
    const float* src = (k8 < 2048u) ? (x + (size_t)m * 2048 + k8)
                                    : (h + (size_t)m * 2048 + (k8 - 2048u));
    float4 a = ((const float4*)src)[0];
    float4 b = ((const float4*)src)[1];
    uint4 o;
    o.x = pack_h2(a.x, a.y); o.y = pack_h2(a.z, a.w);
    o.z = pack_h2(b.x, b.y); o.w = pack_h2(b.z, b.w);
    ((uint4*)g_A)[v] = o;
}

__global__ __launch_bounds__(256) void conv_w_kernel(
    const float* __restrict__ Wi, const float* __restrict__ Wf,
    const float* __restrict__ Wo, const float* __restrict__ Wc) {
    uint32_t v = blockIdx.x * 256u + threadIdx.x;   // 4,194,304 vec8
    uint32_t row  = v >> 9;                         // 0..8191 gate-stacked
    uint32_t k8   = (v & 511u) << 3;
    uint32_t gate = row >> 11;
    uint32_t n    = row & 2047u;
    const float* w = (gate == 0) ? Wi : (gate == 1) ? Wf : (gate == 2) ? Wo : Wc;
    const float4* s = (const float4*)(w + (size_t)n * DDIM + k8);
    float4 a = s[0], b = s[1];
    uint4 o;
    o.x = pack_h2(a.x, a.y); o.y = pack_h2(a.z, a.w);
    o.z = pack_h2(b.x, b.y); o.w = pack_h2(b.z, b.w);
    ((uint4*)g_W)[v] = o;
}

// ---------------------------------------------------------------------------
// Fused GEMM (mma.sync fp16) + LSTM gating
// ---------------------------------------------------------------------------
__device__ __forceinline__ float fsigmoid(float x) {
    return 1.0f / (1.0f + __expf(-x));
}
__device__ __forceinline__ float ftanh(float x) {
    float e = __expf(2.0f * x);            // inf-safe: 1 - 2/(e+1)
    return 1.0f - 2.0f / (e + 1.0f);
}

__global__ __launch_bounds__(256, 1) void lstm_mma_kernel(
    const float* __restrict__ c_prev,
    const float* __restrict__ bi, const float* __restrict__ bff,
    const float* __restrict__ bo, const float* __restrict__ bc,
    float* __restrict__ out) {
    extern __shared__ char smem[];
    const uint32_t sbase = smem_u32(smem);
    const int tid  = threadIdx.x;
    const int warp = tid >> 5;
    const int lane = tid & 31;

    const int mtile = blockIdx.x & 15;     // 16 M tiles of 256
    const int htile = blockIdx.x >> 4;     // 64 H tiles of 32
    const int Mbase = mtile << 8;
    const int Hbase = htile << 5;

    // Bias slice -> SMEM: bs[g*32 + hl]
    if (tid < 128) {
        const float* bp = (tid < 32) ? bi : (tid < 64) ? bff : (tid < 96) ? bo : bc;
        ((float*)smem)[tid] = bp[Hbase + (tid & 31)];
    }

    // ---------------- loader setup (all 256 threads) ----------------
    const int seg = tid & 7;               // 16B segment within 128B row
    const int r0  = tid >> 3;              // 0..31
    const uint32_t swz = (uint32_t)((seg ^ (r0 & 7)) * 16);
    uint32_t aGo[8], bGo[4], aSo[8], bSo[4];
    #pragma unroll
    for (int i = 0; i < 8; i++) {
        const int r = r0 + 32 * i;                       // A tile row
        aGo[i] = (uint32_t)(Mbase + r) * (DDIM * 2) + (uint32_t)(seg * 16);
        aSo[i] = (uint32_t)(r * 128) + swz;
    }
    #pragma unroll
    for (int i = 0; i < 4; i++) {
        const int n  = r0 + 32 * i;                      // B tile row (gate-major)
        const int g  = n >> 5;
        const int hl = n & 31;
        bGo[i] = (uint32_t)(g * HDIM + Hbase + hl) * (DDIM * 2) + (uint32_t)(seg * 16);
        bSo[i] = (uint32_t)(n * 128) + swz + BOFF;
    }
    const char* gA = (const char*)g_A;
    const char* gW = (const char*)g_W;

    // ---------------- mma fragment address setup ----------------
    // A: lanes 0..15 rows (lane%16), seg-half lane/16
    const int aRow   = (warp << 5) + (lane & 15);
    const uint32_t aXor  = (uint32_t)(lane & 7);
    const uint32_t aSegH = (uint32_t)(lane >> 4);
    // B: rows n = (lane&7) + 8*(lane>>4), seg-half (lane>>3)&1
    const int bRow   = (lane & 7) + ((lane >> 4) << 3);
    const uint32_t bSegH = (uint32_t)((lane >> 3) & 1);

    float acc[2][16][4];
    #pragma unroll
    for (int mi = 0; mi < 2; mi++)
        #pragma unroll
        for (int ni = 0; ni < 16; ni++)
            #pragma unroll
            for (int e = 0; e < 4; e++) acc[mi][ni][e] = 0.0f;

    // ---------------- software pipeline ----------------
    auto issue = [&](int c, int s) {
        const uint32_t st = sbase + SOFF + (uint32_t)s * STAGE;
        const uint32_t co = (uint32_t)c << 7;   // c * 128 bytes along K
        #pragma unroll
        for (int i = 0; i < 8; i++) CP_ASYNC16(st + aSo[i], gA + aGo[i] + co);
        #pragma unroll
        for (int i = 0; i < 4; i++) CP_ASYNC16(st + bSo[i], gW + bGo[i] + co);
        CP_COMMIT();
    };

    issue(0, 0);
    issue(1, 1);

    for (int c = 0; c < NCHUNK; c++) {
        CP_WAIT1();                 // chunk c resident
        __syncthreads();
        if (c + 2 < NCHUNK) issue(c + 2, (c + 2) % NST);

        const uint32_t sA = sbase + SOFF + (uint32_t)(c % NST) * STAGE;
        const uint32_t sB = sA + BOFF;
        const uint32_t aBase = sA + (uint32_t)(aRow * 128);
        const uint32_t bBase = sB + (uint32_t)(bRow * 128);

        #pragma unroll
        for (int ks = 0; ks < 4; ks++) {
            uint32_t a0[4], a1[4];
            const uint32_t aswz = (((uint32_t)(2 * ks) + aSegH) ^ aXor) * 16;
            LDSM_X4(a0, aBase + aswz);
            LDSM_X4(a1, aBase + 2048 + aswz);     // +16 rows * 128B
            const uint32_t bswz = (((uint32_t)(2 * ks) + bSegH) ^ aXor) * 16;
            #pragma unroll
            for (int nb = 0; nb < 8; nb++) {
                uint32_t b[4];
                LDSM_X4(b, bBase + (uint32_t)(nb * 2048) + bswz);
                MMA16816(acc[0][2 * nb],     a0, b[0], b[1]);
                MMA16816(acc[0][2 * nb + 1], a0, b[2], b[3]);
                MMA16816(acc[1][2 * nb],     a1, b[0], b[1]);
                MMA16816(acc[1][2 * nb + 1], a1, b[2], b[3]);
            }
        }
    }

    // ---------------- fused LSTM epilogue (register-local gating) ----------------
    // acc element e: row = lane/4 + 8*(e/2), col = 2*(lane%4) + (e&1)
    // fragment ni = 4*gate + nh  -> tile col = 32*gate + 8*nh + coloff
    const float* bs = (const float*)smem;
    #pragma unroll
    for (int mi = 0; mi < 2; mi++) {
        const int mrow0 = Mbase + (warp << 5) + (mi << 4) + (lane >> 2);
        #pragma unroll
        for (int nh = 0; nh < 4; nh++) {
            const int hcol = (nh << 3) + ((lane & 3) << 1);   // 0..30 even
            const float bi0 = bs[hcol],      bi1 = bs[hcol + 1];
            const float bf0 = bs[32 + hcol], bf1 = bs[33 + hcol];
            const float bo0 = bs[64 + hcol], bo1 = bs[65 + hcol];
            const float bc0 = bs[96 + hcol], bc1 = bs[97 + hcol];
            #pragma unroll
            for (int rp = 0; rp < 2; rp++) {
                const int m = mrow0 + (rp << 3);
                const size_t off = (size_t)m * HDIM + (size_t)(Hbase + hcol);
                const float2 cp = *(const float2*)(c_prev + off);
                const float zi0 = acc[mi][nh][2 * rp]     + bi0;
                const float zi1 = acc[mi][nh][2 * rp + 1] + bi1;
                const float zf0 = acc[mi][4 + nh][2 * rp]     + bf0;
                const float zf1 = acc[mi][4 + nh][2 * rp + 1] + bf1;
                const float zo0 = acc[mi][8 + nh][2 * rp]     + bo0;
                const float zo1 = acc[mi][8 + nh][2 * rp + 1] + bo1;
                const float zc0 = acc[mi][12 + nh][2 * rp]     + bc0;
                const float zc1 = acc[mi][12 + nh][2 * rp + 1] + bc1;
                const float ct0 = fsigmoid(zf0) * cp.x + fsigmoid(zi0) * ftanh(zc0);
                const float ct1 = fsigmoid(zf1) * cp.y + fsigmoid(zi1) * ftanh(zc1);
                const float ht0 = fsigmoid(zo0) * ftanh(ct0);
                const float ht1 = fsigmoid(zo1) * ftanh(ct1);
                *(float2*)(out + off) = make_float2(ht0, ht1);
                *(float2*)(out + (size_t)BATCH_N * HDIM + off) = make_float2(ct0, ct1);
            }
        }
    }
}

// ---------------------------------------------------------------------------
// Inputs (metadata order): x_t, h_t_1, c_t_1, W_i, b_i, W_f, b_f, W_o, b_o,
//                          W_c, b_c.  Output: [h_t (B*H), c_t (B*H)] fp32.
// ---------------------------------------------------------------------------
extern "C" void kernel_launch(void* const* d_in, const int* in_sizes, int n_in,
                              void* d_out, int out_size) {
    (void)in_sizes; (void)n_in; (void)out_size;
    const float* x  = (const float*)d_in[0];
    const float* h  = (const float*)d_in[1];
    const float* c  = (const float*)d_in[2];
    const float* Wi = (const float*)d_in[3];
    const float* bi = (const float*)d_in[4];
    const float* Wf = (const float*)d_in[5];
    const float* bf = (const float*)d_in[6];
    const float* Wo = (const float*)d_in[7];
    const float* bo = (const float*)d_in[8];
    const float* Wc = (const float*)d_in[9];
    const float* bc = (const float*)d_in[10];
    float* out = (float*)d_out;

    conv_a_kernel<<<8192, 256>>>(x, h);
    conv_w_kernel<<<16384, 256>>>(Wi, Wf, Wo, Wc);

    cudaFuncSetAttribute(lstm_mma_kernel,
                         cudaFuncAttributeMaxDynamicSharedMemorySize, SMEM_TOTAL);
    lstm_mma_kernel<<<1024, 256, SMEM_TOTAL>>>(c, bi, bf, bo, bc, out);
}

// round 8
// speedup vs baseline: 1.0647x; 1.0647x over previous
#include <cuda_runtime.h>
#include <cuda_fp16.h>
#include <cstdint>
#include <cstddef>

// ---------------------------------------------------------------------------
// Problem dims
// ---------------------------------------------------------------------------
#define BATCH_N 4096
#define DDIM    4096   // input(2048) + hidden(2048)
#define HDIM    2048

// GEMM tile: 256 (M) x 128 (N), BK = 64. 16 warps: 8(M) x 2(N), warp 32x64.
// B tile rows ordered [hblk(2 x 16h) x gate(4) x 16] so each warp's 64 cols
// hold all 4 gates for 16 h-columns -> register-local LSTM gating.
#define BM      256
#define BN      128
#define BK      64
#define NCHUNK  (DDIM / BK)                 // 64
#define NST     3
#define STAGE   49152                        // A 32KB + B 16KB
#define BOFF    32768                        // B tile offset within a stage
#define SOFF    1024                         // stages start (bias in [0,512))
#define SMEM_TOTAL (SOFF + NST * STAGE)      // 148480

// Staged fp16 operands (device globals: no allocation anywhere)
__device__ __align__(16) __half g_A[(size_t)BATCH_N * DDIM];   // 32 MB
__device__ __align__(16) __half g_W[(size_t)4 * HDIM * DDIM];  // 64 MB

// ---------------------------------------------------------------------------
// PTX helpers (all legal at compute_103 base target)
// ---------------------------------------------------------------------------
#define CP_ASYNC16(saddr, gptr) \
    asm volatile("cp.async.cg.shared.global [%0], [%1], 16;" \
                 :: "r"(saddr), "l"(gptr) : "memory")
#define CP_COMMIT() asm volatile("cp.async.commit_group;" ::: "memory")
#define CP_WAIT1()  asm volatile("cp.async.wait_group 1;"  ::: "memory")

#define LDSM_X4(r, addr)                                                      \
    asm volatile("ldmatrix.sync.aligned.m8n8.x4.shared.b16 {%0,%1,%2,%3}, [%4];" \
                 : "=r"((r)[0]), "=r"((r)[1]), "=r"((r)[2]), "=r"((r)[3])      \
                 : "r"(addr))

#define MMA16816(d, a, b0, b1)                                                \
    asm volatile(                                                             \
        "mma.sync.aligned.m16n8k16.row.col.f32.f16.f16.f32 "                  \
        "{%0,%1,%2,%3}, {%4,%5,%6,%7}, {%8,%9}, {%0,%1,%2,%3};"               \
        : "+f"((d)[0]), "+f"((d)[1]), "+f"((d)[2]), "+f"((d)[3])              \
        : "r"((a)[0]), "r"((a)[1]), "r"((a)[2]), "r"((a)[3]),                 \
          "r"(b0), "r"(b1))

__device__ __forceinline__ uint32_t smem_u32(const void* p) {
    return (uint32_t)__cvta_generic_to_shared(p);
}

// ---------------------------------------------------------------------------
// fp32 -> fp16 staging kernels
// ---------------------------------------------------------------------------
__device__ __forceinline__ uint32_t pack_h2(float lo, float hi) {
    __half2 t = __floats2half2_rn(lo, hi);  // .x = lower address
    return *reinterpret_cast<uint32_t*>(&t);
}

__global__ __launch_bounds__(256) void conv_a_kernel(
    const float* __restrict__ x, const float* __restrict__ h) {
    uint32_t v = blockIdx.x * 256u + threadIdx.x;   // 2,097,152 vec8
    uint32_t m  = v >> 9;
    uint32_t k8 = (v & 511u) << 3;
    const float* src = (k8 < 2048u) ? (x + (size_t)m * 2048 + k8)
                                    : (h + (size_t)m * 2048 + (k8 - 2048u));
    float4 a = ((const float4*)src)[0];
    float4 b = ((const float4*)src)[1];
    uint4 o;
    o.x = pack_h2(a.x, a.y); o.y = pack_h2(a.z, a.w);
    o.z = pack_h2(b.x, b.y); o.w = pack_h2(b.z, b.w);
    ((uint4*)g_A)[v] = o;
}

__global__ __launch_bounds__(256) void conv_w_kernel(
    const float* __restrict__ Wi, const float* __restrict__ Wf,
    const float* __restrict__ Wo, const float* __restrict__ Wc) {
    uint32_t v = blockIdx.x * 256u + threadIdx.x;   // 4,194,304 vec8
    uint32_t row  = v >> 9;                         // 0..8191 gate-stacked
    uint32_t k8   = (v & 511u) << 3;
    uint32_t gate = row >> 11;
    uint32_t n    = row & 2047u;
    const float* w = (gate == 0) ? Wi : (gate == 1) ? Wf : (gate == 2) ? Wo : Wc;
    const float4* s = (const float4*)(w + (size_t)n * DDIM + k8);
    float4 a = s[0], b = s[1];
    uint4 o;
    o.x = pack_h2(a.x, a.y); o.y = pack_h2(a.z, a.w);
    o.z = pack_h2(b.x, b.y); o.w = pack_h2(b.z, b.w);
    ((uint4*)g_W)[v] = o;
}

// ---------------------------------------------------------------------------
// Fused GEMM (mma.sync fp16) + LSTM gating
// ---------------------------------------------------------------------------
__device__ __forceinline__ float fsigmoid(float x) {
    return 1.0f / (1.0f + __expf(-x));
}
__device__ __forceinline__ float ftanh(float x) {
    float e = __expf(2.0f * x);            // inf-safe: 1 - 2/(e+1)
    return 1.0f - 2.0f / (e + 1.0f);
}

__global__ __launch_bounds__(512, 1) void lstm_mma_kernel(
    const float* __restrict__ c_prev,
    const float* __restrict__ bi, const float* __restrict__ bff,
    const float* __restrict__ bo, const float* __restrict__ bc,
    float* __restrict__ out) {
    extern __shared__ char smem[];
    const uint32_t sbase = smem_u32(smem);
    const int tid  = threadIdx.x;
    const int warp = tid >> 5;
    const int lane = tid & 31;

    const int mtile = blockIdx.x & 15;     // 16 M tiles of 256 (fast-varying)
    const int htile = blockIdx.x >> 4;     // 64 H tiles of 32
    const int Mbase = mtile << 8;
    const int Hbase = htile << 5;

    // Bias slice -> SMEM: bs[g*32 + hl], hl in [0,32)
    if (tid < 128) {
        const float* bp = (tid < 32) ? bi : (tid < 64) ? bff : (tid < 96) ? bo : bc;
        ((float*)smem)[tid] = bp[Hbase + (tid & 31)];
    }

    // ---------------- loader setup (all 512 threads) ----------------
    const int seg = tid & 7;               // 16B segment within 128B row
    const int r0  = tid >> 3;              // 0..63
    const uint32_t swz = (uint32_t)((seg ^ (r0 & 7)) * 16);
    uint32_t aGo[4], bGo[2], aSo[4], bSo[2];
    #pragma unroll
    for (int i = 0; i < 4; i++) {
        const int r = r0 + 64 * i;                       // A tile row 0..255
        aGo[i] = (uint32_t)(Mbase + r) * (DDIM * 2) + (uint32_t)(seg * 16);
        aSo[i] = (uint32_t)(r * 128) + swz;
    }
    #pragma unroll
    for (int i = 0; i < 2; i++) {
        const int n = r0 + 64 * i;                       // B tile row 0..127
        // row order: hblk = n>>6, gate = (n>>4)&3, hl16 = n&15
        const int hblk = i;
        const int gate = (r0 >> 4) & 3;
        const int hl16 = r0 & 15;
        const int grow = gate * HDIM + Hbase + hblk * 16 + hl16;
        bGo[i] = (uint32_t)grow * (DDIM * 2) + (uint32_t)(seg * 16);
        bSo[i] = (uint32_t)(n * 128) + swz + BOFF;
    }
    const char* gA = (const char*)g_A;
    const char* gW = (const char*)g_W;

    // ---------------- mma fragment address setup ----------------
    // warp tile: M rows [(warp&7)*32, +32), B rows [(warp>>3)*64, +64)
    const int aRow   = ((warp & 7) << 5) + (lane & 15);
    const uint32_t aXor  = (uint32_t)(lane & 7);
    const uint32_t aSegH = (uint32_t)(lane >> 4);
    const int bRow   = ((warp >> 3) << 6) + (lane & 7) + ((lane >> 4) << 3);
    const uint32_t bSegH = (uint32_t)((lane >> 3) & 1);

    float acc[2][8][4];
    #pragma unroll
    for (int mi = 0; mi < 2; mi++)
        #pragma unroll
        for (int ni = 0; ni < 8; ni++)
            #pragma unroll
            for (int e = 0; e < 4; e++) acc[mi][ni][e] = 0.0f;

    // ---------------- software pipeline ----------------
    auto issue = [&](int c, int s) {
        const uint32_t st = sbase + SOFF + (uint32_t)s * STAGE;
        const uint32_t co = (uint32_t)c << 7;   // c * 128 bytes along K
        #pragma unroll
        for (int i = 0; i < 4; i++) CP_ASYNC16(st + aSo[i], gA + aGo[i] + co);
        #pragma unroll
        for (int i = 0; i < 2; i++) CP_ASYNC16(st + bSo[i], gW + bGo[i] + co);
        CP_COMMIT();
    };

    issue(0, 0);
    issue(1, 1);

    for (int c = 0; c < NCHUNK; c++) {
        CP_WAIT1();                 // chunk c resident
        __syncthreads();
        if (c + 2 < NCHUNK) issue(c + 2, (c + 2) % NST);

        const uint32_t sA = sbase + SOFF + (uint32_t)(c % NST) * STAGE;
        const uint32_t sB = sA + BOFF;
        const uint32_t aBase = sA + (uint32_t)(aRow * 128);
        const uint32_t bBase = sB + (uint32_t)(bRow * 128);

        #pragma unroll
        for (int ks = 0; ks < 4; ks++) {
            uint32_t a0[4], a1[4];
            const uint32_t aswz = (((uint32_t)(2 * ks) + aSegH) ^ aXor) * 16;
            LDSM_X4(a0, aBase + aswz);
            LDSM_X4(a1, aBase + 2048 + aswz);     // +16 rows * 128B
            const uint32_t bswz = (((uint32_t)(2 * ks) + bSegH) ^ aXor) * 16;
            #pragma unroll
            for (int nb = 0; nb < 4; nb++) {      // nb == gate
                uint32_t b[4];
                LDSM_X4(b, bBase + (uint32_t)(nb * 2048) + bswz);
                MMA16816(acc[0][2 * nb],     a0, b[0], b[1]);
                MMA16816(acc[0][2 * nb + 1], a0, b[2], b[3]);
                MMA16816(acc[1][2 * nb],     a1, b[0], b[1]);
                MMA16816(acc[1][2 * nb + 1], a1, b[2], b[3]);
            }
        }
    }

    // ---------------- fused LSTM epilogue (register-local gating) ----------------
    // acc[mi][2*gate + hc][e]: row = (warp&7)*32 + mi*16 + 8*(e>>1) + lane/4,
    // h col = (warp>>3)*16 + hc*8 + 2*(lane&3) + (e&1)
    const float* bs = (const float*)smem;
    #pragma unroll
    for (int mi = 0; mi < 2; mi++) {
        const int mrow0 = Mbase + ((warp & 7) << 5) + (mi << 4) + (lane >> 2);
        #pragma unroll
        for (int hc = 0; hc < 2; hc++) {
            const int hl = ((warp >> 3) << 4) + (hc << 3) + ((lane & 3) << 1);
            const float bi0 = bs[hl],      bi1 = bs[hl + 1];
            const float bf0 = bs[32 + hl], bf1 = bs[33 + hl];
            const float bo0 = bs[64 + hl], bo1 = bs[65 + hl];
            const float bc0 = bs[96 + hl], bc1 = bs[97 + hl];
            #pragma unroll
            for (int rp = 0; rp < 2; rp++) {
                const int m = mrow0 + (rp << 3);
                const size_t off = (size_t)m * HDIM + (size_t)(Hbase + hl);
                const float2 cp = *(const float2*)(c_prev + off);
                const float zi0 = acc[mi][hc][2 * rp]         + bi0;
                const float zi1 = acc[mi][hc][2 * rp + 1]     + bi1;
                const float zf0 = acc[mi][2 + hc][2 * rp]     + bf0;
                const float zf1 = acc[mi][2 + hc][2 * rp + 1] + bf1;
                const float zo0 = acc[mi][4 + hc][2 * rp]     + bo0;
                const float zo1 = acc[mi][4 + hc][2 * rp + 1] + bo1;
                const float zc0 = acc[mi][6 + hc][2 * rp]     + bc0;
                const float zc1 = acc[mi][6 + hc][2 * rp + 1] + bc1;
                const float ct0 = fsigmoid(zf0) * cp.x + fsigmoid(zi0) * ftanh(zc0);
                const float ct1 = fsigmoid(zf1) * cp.y + fsigmoid(zi1) * ftanh(zc1);
                const float ht0 = fsigmoid(zo0) * ftanh(ct0);
                const float ht1 = fsigmoid(zo1) * ftanh(ct1);
                *(float2*)(out + off) = make_float2(ht0, ht1);
                *(float2*)(out + (size_t)BATCH_N * HDIM + off) = make_float2(ct0, ct1);
            }
        }
    }
}

// ---------------------------------------------------------------------------
// Inputs (metadata order): x_t, h_t_1, c_t_1, W_i, b_i, W_f, b_f, W_o, b_o,
//                          W_c, b_c.  Output: [h_t (B*H), c_t (B*H)] fp32.
// ---------------------------------------------------------------------------
extern "C" void kernel_launch(void* const* d_in, const int* in_sizes, int n_in,
                              void* d_out, int out_size) {
    (void)in_sizes; (void)n_in; (void)out_size;
    const float* x  = (const float*)d_in[0];
    const float* h  = (const float*)d_in[1];
    const float* c  = (const float*)d_in[2];
    const float* Wi = (const float*)d_in[3];
    const float* bi = (const float*)d_in[4];
    const float* Wf = (const float*)d_in[5];
    const float* bf = (const float*)d_in[6];
    const float* Wo = (const float*)d_in[7];
    const float* bo = (const float*)d_in[8];
    const float* Wc = (const float*)d_in[9];
    const float* bc = (const float*)d_in[10];
    float* out = (float*)d_out;

    conv_a_kernel<<<8192, 256>>>(x, h);
    conv_w_kernel<<<16384, 256>>>(Wi, Wf, Wo, Wc);

    cudaFuncSetAttribute(lstm_mma_kernel,
                         cudaFuncAttributeMaxDynamicSharedMemorySize, SMEM_TOTAL);
    lstm_mma_kernel<<<1024, 512, SMEM_TOTAL>>>(c, bi, bf, bo, bc, out);
}

// round 10
// speedup vs baseline: 1.1010x; 1.0342x over previous
#include <cuda_runtime.h>
#include <cuda_fp16.h>
#include <cstdint>
#include <cstddef>

// ---------------------------------------------------------------------------
// Problem dims
// ---------------------------------------------------------------------------
#define BATCH_N 4096
#define DDIM    4096   // input(2048) + hidden(2048)
#define HDIM    2048

// GEMM tile: 256 (M) x 128 (N), BK = 64. 16 warps: 8(M) x 2(N), warp 32x64.
// B tile rows ordered [hblk(2 x 16h) x gate(4) x 16] so each warp's 64 cols
// hold all 4 gates for 16 h-columns -> register-local LSTM gating.
#define BM      256
#define BN      128
#define BK      64
#define NCHUNK  (DDIM / BK)                 // 64
#define NST     3
#define STAGE   49152                        // A 32KB + B 16KB
#define BOFF    32768                        // B tile offset within a stage
#define SOFF    1024                         // stages start (bias+mbars below)
#define SMEM_TOTAL (SOFF + NST * STAGE)      // 148480

// Staged fp16 operands (device globals: no allocation anywhere)
__device__ __align__(16) __half g_A[(size_t)BATCH_N * DDIM];   // 32 MB
__device__ __align__(16) __half g_W[(size_t)4 * HDIM * DDIM];  // 64 MB

// ---------------------------------------------------------------------------
// PTX helpers (all legal at compute_103 base target)
// ---------------------------------------------------------------------------
#define CP_ASYNC16(saddr, gptr) \
    asm volatile("cp.async.cg.shared.global [%0], [%1], 16;" \
                 :: "r"(saddr), "l"(gptr) : "memory")

// mbarrier ops (sm_80 base features)
#define MBARRIER_INIT(addr, cnt) \
    asm volatile("mbarrier.init.shared.b64 [%0], %1;" :: "r"(addr), "r"(cnt) : "memory")
#define MBARRIER_ARRIVE(addr) \
    asm volatile("mbarrier.arrive.shared.b64 _, [%0];" :: "r"(addr) : "memory")
// .noinc is REQUIRED: the default form increments pending count then arrives
// (net zero) and the barrier would never flip -> deadlock (seen in R9).
#define CP_MBARRIER_ARRIVE(addr) \
    asm volatile("cp.async.mbarrier.arrive.noinc.shared.b64 [%0];" :: "r"(addr) : "memory")

#define MBARRIER_WAIT(mbar, phase_parity) do {                                 \
    uint32_t _mbar = (uint32_t)(mbar);                                         \
    uint32_t _parity = (uint32_t)(phase_parity);                               \
    uint32_t _done;                                                            \
    asm volatile(                                                              \
        "{\n\t.reg .pred p;\n\t"                                               \
        "mbarrier.try_wait.parity.acquire.cta.shared::cta.b64 p, [%1], %2;\n\t"\
        "selp.b32 %0, 1, 0, p;\n\t}"                                           \
        : "=r"(_done) : "r"(_mbar), "r"(_parity) : "memory");                   \
    if (!_done) {                                                              \
        asm volatile(                                                          \
            "{\n\t.reg .pred P1;\n\t"                                          \
            "WAIT_LOOP_%=:\n\t"                                                \
            "mbarrier.try_wait.parity.acquire.cta.shared::cta.b64 P1, [%0], %1, 0x989680;\n\t" \
            "@P1 bra.uni WAIT_DONE_%=;\n\t"                                    \
            "bra.uni WAIT_LOOP_%=;\n\t"                                        \
            "WAIT_DONE_%=:\n\t}"                                               \
            :: "r"(_mbar), "r"(_parity) : "memory");                           \
    }                                                                          \
} while (0)

#define LDSM_X4(r, addr)                                                      \
    asm volatile("ldmatrix.sync.aligned.m8n8.x4.shared.b16 {%0,%1,%2,%3}, [%4];" \
                 : "=r"((r)[0]), "=r"((r)[1]), "=r"((r)[2]), "=r"((r)[3])      \
                 : "r"(addr))

#define MMA16816(d, a, b0, b1)                                                \
    asm volatile(                                                             \
        "mma.sync.aligned.m16n8k16.row.col.f32.f16.f16.f32 "                  \
        "{%0,%1,%2,%3}, {%4,%5,%6,%7}, {%8,%9}, {%0,%1,%2,%3};"               \
        : "+f"((d)[0]), "+f"((d)[1]), "+f"((d)[2]), "+f"((d)[3])              \
        : "r"((a)[0]), "r"((a)[1]), "r"((a)[2]), "r"((a)[3]),                 \
          "r"(b0), "r"(b1))

__device__ __forceinline__ uint32_t smem_u32(const void* p) {
    return (uint32_t)__cvta_generic_to_shared(p);
}

// ---------------------------------------------------------------------------
// fp32 -> fp16 staging kernels
// ---------------------------------------------------------------------------
__device__ __forceinline__ uint32_t pack_h2(float lo, float hi) {
    __half2 t = __floats2half2_rn(lo, hi);  // .x = lower address
    return *reinterpret_cast<uint32_t*>(&t);
}

__global__ __launch_bounds__(256) void conv_a_kernel(
    const float* __restrict__ x, const float* __restrict__ h) {
    uint32_t v = blockIdx.x * 256u + threadIdx.x;   // 2,097,152 vec8
    uint32_t m  = v >> 9;
    uint32_t k8 = (v & 511u) << 3;
    const float* src = (k8 < 2048u) ? (x + (size_t)m * 2048 + k8)
                                    : (h + (size_t)m * 2048 + (k8 - 2048u));
    float4 a = ((const float4*)src)[0];
    float4 b = ((const float4*)src)[1];
    uint4 o;
    o.x = pack_h2(a.x, a.y); o.y = pack_h2(a.z, a.w);
    o.z = pack_h2(b.x, b.y); o.w = pack_h2(b.z, b.w);
    ((uint4*)g_A)[v] = o;
}

__global__ __launch_bounds__(256) void conv_w_kernel(
    const float* __restrict__ Wi, const float* __restrict__ Wf,
    const float* __restrict__ Wo, const float* __restrict__ Wc) {
    uint32_t v = blockIdx.x * 256u + threadIdx.x;   // 4,194,304 vec8
    uint32_t row  = v >> 9;                         // 0..8191 gate-stacked
    uint32_t k8   = (v & 511u) << 3;
    uint32_t gate = row >> 11;
    uint32_t n    = row & 2047u;
    const float* w = (gate == 0) ? Wi : (gate == 1) ? Wf : (gate == 2) ? Wo : Wc;
    const float4* s = (const float4*)(w + (size_t)n * DDIM + k8);
    float4 a = s[0], b = s[1];
    uint4 o;
    o.x = pack_h2(a.x, a.y); o.y = pack_h2(a.z, a.w);
    o.z = pack_h2(b.x, b.y); o.w = pack_h2(b.z, b.w);
    ((uint4*)g_W)[v] = o;
}

// ---------------------------------------------------------------------------
// Fused GEMM (mma.sync fp16) + LSTM gating
// ---------------------------------------------------------------------------
__device__ __forceinline__ float fsigmoid(float x) {
    return 1.0f / (1.0f + __expf(-x));
}
__device__ __forceinline__ float ftanh(float x) {
    float e = __expf(2.0f * x);            // inf-safe: 1 - 2/(e+1)
    return 1.0f - 2.0f / (e + 1.0f);
}

// SMEM map: [0,512) bias | [512,536) full mbars x3 | [536,560) empty mbars x3
//           [1024, ...) 3 x 48KB stages
__global__ __launch_bounds__(512, 1) void lstm_mma_kernel(
    const float* __restrict__ c_prev,
    const float* __restrict__ bi, const float* __restrict__ bff,
    const float* __restrict__ bo, const float* __restrict__ bc,
    float* __restrict__ out) {
    extern __shared__ char smem[];
    const uint32_t sbase = smem_u32(smem);
    const int tid  = threadIdx.x;
    const int warp = tid >> 5;
    const int lane = tid & 31;

    const int mtile = blockIdx.x & 15;     // 16 M tiles of 256 (fast-varying)
    const int htile = blockIdx.x >> 4;     // 64 H tiles of 32
    const int Mbase = mtile << 8;
    const int Hbase = htile << 5;

    // Bias slice -> SMEM: bs[g*32 + hl], hl in [0,32)
    if (tid < 128) {
        const float* bp = (tid < 32) ? bi : (tid < 64) ? bff : (tid < 96) ? bo : bc;
        ((float*)smem)[tid] = bp[Hbase + (tid & 31)];
    }
    if (tid == 0) {
        #pragma unroll
        for (int s = 0; s < NST; s++) {
            MBARRIER_INIT(sbase + 512 + 8 * s, 512);   // full: cp.async arrivals
            MBARRIER_INIT(sbase + 536 + 8 * s, 512);   // empty: reader-done
        }
    }

    // ---------------- loader setup (all 512 threads) ----------------
    const int seg = tid & 7;               // 16B segment within 128B row
    const int r0  = tid >> 3;              // 0..63
    const uint32_t swz = (uint32_t)((seg ^ (r0 & 7)) * 16);
    uint32_t aGo[4], bGo[2], aSo[4], bSo[2];
    #pragma unroll
    for (int i = 0; i < 4; i++) {
        const int r = r0 + 64 * i;                       // A tile row 0..255
        aGo[i] = (uint32_t)(Mbase + r) * (DDIM * 2) + (uint32_t)(seg * 16);
        aSo[i] = (uint32_t)(r * 128) + swz;
    }
    #pragma unroll
    for (int i = 0; i < 2; i++) {
        const int n = r0 + 64 * i;                       // B tile row 0..127
        // row order: hblk = n>>6, gate = (n>>4)&3, hl16 = n&15
        const int hblk = i;
        const int gate = (r0 >> 4) & 3;
        const int hl16 = r0 & 15;
        const int grow = gate * HDIM + Hbase + hblk * 16 + hl16;
        bGo[i] = (uint32_t)grow * (DDIM * 2) + (uint32_t)(seg * 16);
        bSo[i] = (uint32_t)(n * 128) + swz + BOFF;
    }
    const char* gA = (const char*)g_A;
    const char* gW = (const char*)g_W;

    // ---------------- mma fragment address setup ----------------
    // warp tile: M rows [(warp&7)*32, +32), B rows [(warp>>3)*64, +64)
    const int aRow   = ((warp & 7) << 5) + (lane & 15);
    const uint32_t aXor  = (uint32_t)(lane & 7);
    const uint32_t aSegH = (uint32_t)(lane >> 4);
    const int bRow   = ((warp >> 3) << 6) + (lane & 7) + ((lane >> 4) << 3);
    const uint32_t bSegH = (uint32_t)((lane >> 3) & 1);

    float acc[2][8][4];
    #pragma unroll
    for (int mi = 0; mi < 2; mi++)
        #pragma unroll
        for (int ni = 0; ni < 8; ni++)
            #pragma unroll
            for (int e = 0; e < 4; e++) acc[mi][ni][e] = 0.0f;

    auto issue = [&](int c, int s) {
        const uint32_t st = sbase + SOFF + (uint32_t)s * STAGE;
        const uint32_t co = (uint32_t)c << 7;   // c * 128 bytes along K
        #pragma unroll
        for (int i = 0; i < 4; i++) CP_ASYNC16(st + aSo[i], gA + aGo[i] + co);
        #pragma unroll
        for (int i = 0; i < 2; i++) CP_ASYNC16(st + bSo[i], gW + bGo[i] + co);
    };

    __syncthreads();    // mbarriers initialized + bias visible

    // Prologue: fill stages 0 and 1.
    issue(0, 0);
    CP_MBARRIER_ARRIVE(sbase + 512 + 0);
    issue(1, 1);
    CP_MBARRIER_ARRIVE(sbase + 512 + 8);

    for (int c = 0; c < NCHUNK; c++) {
        // Produce chunk c+2 (stage (c+2)%3). Empty-wait: readers of chunk c-1
        // (same stage) must all have arrived. Our own arrival happened at the
        // end of iteration c-1, so this only waits on slower warps.
        const int j = c + 2;
        if (j < NCHUNK) {
            const int sj = j % NST;
            if (j >= NST) MBARRIER_WAIT(sbase + 536 + 8 * sj,
                                        (uint32_t)((j / NST - 1) & 1));
            issue(j, sj);
            CP_MBARRIER_ARRIVE(sbase + 512 + 8 * sj);
        }

        // Consume chunk c.
        const int s = c % NST;
        MBARRIER_WAIT(sbase + 512 + 8 * s, (uint32_t)((c / NST) & 1));

        const uint32_t sA = sbase + SOFF + (uint32_t)s * STAGE;
        const uint32_t sB = sA + BOFF;
        const uint32_t aBase = sA + (uint32_t)(aRow * 128);
        const uint32_t bBase = sB + (uint32_t)(bRow * 128);

        #pragma unroll
        for (int ks = 0; ks < 4; ks++) {
            uint32_t a0[4], a1[4];
            const uint32_t aswz = (((uint32_t)(2 * ks) + aSegH) ^ aXor) * 16;
            LDSM_X4(a0, aBase + aswz);
            LDSM_X4(a1, aBase + 2048 + aswz);     // +16 rows * 128B
            const uint32_t bswz = (((uint32_t)(2 * ks) + bSegH) ^ aXor) * 16;
            #pragma unroll
            for (int nb = 0; nb < 4; nb++) {      // nb == gate
                uint32_t b[4];
                LDSM_X4(b, bBase + (uint32_t)(nb * 2048) + bswz);
                MMA16816(acc[0][2 * nb],     a0, b[0], b[1]);
                MMA16816(acc[0][2 * nb + 1], a0, b[2], b[3]);
                MMA16816(acc[1][2 * nb],     a1, b[0], b[1]);
                MMA16816(acc[1][2 * nb + 1], a1, b[2], b[3]);
            }
        }

        MBARRIER_ARRIVE(sbase + 536 + 8 * s);   // reader-done for stage s
    }

    // ---------------- fused LSTM epilogue (register-local gating) ----------------
    // acc[mi][2*gate + hc][e]: row = (warp&7)*32 + mi*16 + 8*(e>>1) + lane/4,
    // h col = (warp>>3)*16 + hc*8 + 2*(lane&3) + (e&1)
    const float* bs = (const float*)smem;
    #pragma unroll
    for (int mi = 0; mi < 2; mi++) {
        const int mrow0 = Mbase + ((warp & 7) << 5) + (mi << 4) + (lane >> 2);
        #pragma unroll
        for (int hc = 0; hc < 2; hc++) {
            const int hl = ((warp >> 3) << 4) + (hc << 3) + ((lane & 3) << 1);
            const float bi0 = bs[hl],      bi1 = bs[hl + 1];
            const float bf0 = bs[32 + hl], bf1 = bs[33 + hl];
            const float bo0 = bs[64 + hl], bo1 = bs[65 + hl];
            const float bc0 = bs[96 + hl], bc1 = bs[97 + hl];
            #pragma unroll
            for (int rp = 0; rp < 2; rp++) {
                const int m = mrow0 + (rp << 3);
                const size_t off = (size_t)m * HDIM + (size_t)(Hbase + hl);
                const float2 cp = *(const float2*)(c_prev + off);
                const float zi0 = acc[mi][hc][2 * rp]         + bi0;
                const float zi1 = acc[mi][hc][2 * rp + 1]     + bi1;
                const float zf0 = acc[mi][2 + hc][2 * rp]     + bf0;
                const float zf1 = acc[mi][2 + hc][2 * rp + 1] + bf1;
                const float zo0 = acc[mi][4 + hc][2 * rp]     + bo0;
                const float zo1 = acc[mi][4 + hc][2 * rp + 1] + bo1;
                const float zc0 = acc[mi][6 + hc][2 * rp]     + bc0;
                const float zc1 = acc[mi][6 + hc][2 * rp + 1] + bc1;
                const float ct0 = fsigmoid(zf0) * cp.x + fsigmoid(zi0) * ftanh(zc0);
                const float ct1 = fsigmoid(zf1) * cp.y + fsigmoid(zi1) * ftanh(zc1);
                const float ht0 = fsigmoid(zo0) * ftanh(ct0);
                const float ht1 = fsigmoid(zo1) * ftanh(ct1);
                *(float2*)(out + off) = make_float2(ht0, ht1);
                *(float2*)(out + (size_t)BATCH_N * HDIM + off) = make_float2(ct0, ct1);
            }
        }
    }
}

// ---------------------------------------------------------------------------
// Inputs (metadata order): x_t, h_t_1, c_t_1, W_i, b_i, W_f, b_f, W_o, b_o,
//                          W_c, b_c.  Output: [h_t (B*H), c_t (B*H)] fp32.
// ---------------------------------------------------------------------------
extern "C" void kernel_launch(void* const* d_in, const int* in_sizes, int n_in,
                              void* d_out, int out_size) {
    (void)in_sizes; (void)n_in; (void)out_size;
    const float* x  = (const float*)d_in[0];
    const float* h  = (const float*)d_in[1];
    const float* c  = (const float*)d_in[2];
    const float* Wi = (const float*)d_in[3];
    const float* bi = (const float*)d_in[4];
    const float* Wf = (const float*)d_in[5];
    const float* bf = (const float*)d_in[6];
    const float* Wo = (const float*)d_in[7];
    const float* bo = (const float*)d_in[8];
    const float* Wc = (const float*)d_in[9];
    const float* bc = (const float*)d_in[10];
    float* out = (float*)d_out;

    conv_a_kernel<<<8192, 256>>>(x, h);
    conv_w_kernel<<<16384, 256>>>(Wi, Wf, Wo, Wc);

    cudaFuncSetAttribute(lstm_mma_kernel,
                         cudaFuncAttributeMaxDynamicSharedMemorySize, SMEM_TOTAL);
    lstm_mma_kernel<<<1024, 512, SMEM_TOTAL>>>(c, bi, bf, bo, bc, out);
}

// round 12
// speedup vs baseline: 1.1750x; 1.0672x over previous
#include <cuda_runtime.h>
#include <cuda_fp16.h>
#include <cstdint>
#include <cstddef>

// ---------------------------------------------------------------------------
// Problem dims
// ---------------------------------------------------------------------------
#define BATCH_N 4096
#define DDIM    4096   // input(2048) + hidden(2048)
#define HDIM    2048

// GEMM tile: 256 (M) x 128 (N), BK = 64. 8 warps: 4(M) x 2(N), warp 64x64.
// B tile rows ordered [hblk(2 x 16h) x gate(4) x 16] so each warp's 64 cols
// hold all 4 gates for 16 h-columns -> register-local LSTM gating.
#define BM      256
#define BN      128
#define BK      64
#define NCHUNK  (DDIM / BK)                 // 64
#define NST     3
#define STAGE   49152                        // A 32KB + B 16KB
#define BOFF    32768                        // B tile offset within a stage
#define SOFF    1024                         // stages start (bias+mbars below)
#define SMEM_TOTAL (SOFF + NST * STAGE)      // 148480
#define NTHREADS 256

// Staged fp16 operands (device globals: no allocation anywhere)
__device__ __align__(16) __half g_A[(size_t)BATCH_N * DDIM];   // 32 MB
__device__ __align__(16) __half g_W[(size_t)4 * HDIM * DDIM];  // 64 MB

// ---------------------------------------------------------------------------
// PTX helpers (all legal at compute_103 base target)
// ---------------------------------------------------------------------------
#define CP_ASYNC16(saddr, gptr) \
    asm volatile("cp.async.cg.shared.global [%0], [%1], 16;" \
                 :: "r"(saddr), "l"(gptr) : "memory")

#define MBARRIER_INIT(addr, cnt) \
    asm volatile("mbarrier.init.shared.b64 [%0], %1;" :: "r"(addr), "r"(cnt) : "memory")
#define MBARRIER_ARRIVE(addr) \
    asm volatile("mbarrier.arrive.shared.b64 _, [%0];" :: "r"(addr) : "memory")
// .noinc is REQUIRED: default form increments pending count then arrives
// (net zero) -> barrier never flips -> deadlock (seen in R9).
#define CP_MBARRIER_ARRIVE(addr) \
    asm volatile("cp.async.mbarrier.arrive.noinc.shared.b64 [%0];" :: "r"(addr) : "memory")

#define MBARRIER_WAIT(mbar, phase_parity) do {                                 \
    uint32_t _mbar = (uint32_t)(mbar);                                         \
    uint32_t _parity = (uint32_t)(phase_parity);                               \
    uint32_t _done;                                                            \
    asm volatile(                                                              \
        "{\n\t.reg .pred p;\n\t"                                               \
        "mbarrier.try_wait.parity.acquire.cta.shared::cta.b64 p, [%1], %2;\n\t"\
        "selp.b32 %0, 1, 0, p;\n\t}"                                           \
        : "=r"(_done) : "r"(_mbar), "r"(_parity) : "memory");                   \
    if (!_done) {                                                              \
        asm volatile(                                                          \
            "{\n\t.reg .pred P1;\n\t"                                          \
            "WAIT_LOOP_%=:\n\t"                                                \
            "mbarrier.try_wait.parity.acquire.cta.shared::cta.b64 P1, [%0], %1, 0x989680;\n\t" \
            "@P1 bra.uni WAIT_DONE_%=;\n\t"                                    \
            "bra.uni WAIT_LOOP_%=;\n\t"                                        \
            "WAIT_DONE_%=:\n\t}"                                               \
            :: "r"(_mbar), "r"(_parity) : "memory");                           \
    }                                                                          \
} while (0)

#define LDSM_X4(r, addr)                                                      \
    asm volatile("ldmatrix.sync.aligned.m8n8.x4.shared.b16 {%0,%1,%2,%3}, [%4];" \
                 : "=r"((r)[0]), "=r"((r)[1]), "=r"((r)[2]), "=r"((r)[3])      \
                 : "r"(addr))

#define MMA16816(d, a, b0, b1)                                                \
    asm volatile(                                                             \
        "mma.sync.aligned.m16n8k16.row.col.f32.f16.f16.f32 "                  \
        "{%0,%1,%2,%3}, {%4,%5,%6,%7}, {%8,%9}, {%0,%1,%2,%3};"               \
        : "+f"((d)[0]), "+f"((d)[1]), "+f"((d)[2]), "+f"((d)[3])              \
        : "r"((a)[0]), "r"((a)[1]), "r"((a)[2]), "r"((a)[3]),                 \
          "r"(b0), "r"(b1))

__device__ __forceinline__ uint32_t smem_u32(const void* p) {
    return (uint32_t)__cvta_generic_to_shared(p);
}

// ---------------------------------------------------------------------------
// fp32 -> fp16 staging (single fused kernel: blocks [0,8192) do A, rest do W)
// ---------------------------------------------------------------------------
__device__ __forceinline__ uint32_t pack_h2(float lo, float hi) {
    __half2 t = __floats2half2_rn(lo, hi);  // .x = lower address
    return *reinterpret_cast<uint32_t*>(&t);
}

__global__ __launch_bounds__(256) void conv_kernel(
    const float* __restrict__ x, const float* __restrict__ h,
    const float* __restrict__ Wi, const float* __restrict__ Wf,
    const float* __restrict__ Wo, const float* __restrict__ Wc) {
    if (blockIdx.x < 8192) {
        uint32_t v = blockIdx.x * 256u + threadIdx.x;   // 2,097,152 vec8
        uint32_t m  = v >> 9;
        uint32_t k8 = (v & 511u) << 3;
        const float* src = (k8 < 2048u) ? (x + (size_t)m * 2048 + k8)
                                        : (h + (size_t)m * 2048 + (k8 - 2048u));
        float4 a = ((const float4*)src)[0];
        float4 b = ((const float4*)src)[1];
        uint4 o;
        o.x = pack_h2(a.x, a.y); o.y = pack_h2(a.z, a.w);
        o.z = pack_h2(b.x, b.y); o.w = pack_h2(b.z, b.w);
        ((uint4*)g_A)[v] = o;
    } else {
        uint32_t v = (blockIdx.x - 8192) * 256u + threadIdx.x;  // 4,194,304 vec8
        uint32_t row  = v >> 9;                         // 0..8191 gate-stacked
        uint32_t k8   = (v & 511u) << 3;
        uint32_t gate = row >> 11;
        uint32_t n    = row & 2047u;
        const float* w = (gate == 0) ? Wi : (gate == 1) ? Wf : (gate == 2) ? Wo : Wc;
        const float4* s = (const float4*)(w + (size_t)n * DDIM + k8);
        float4 a = s[0], b = s[1];
        uint4 o;
        o.x = pack_h2(a.x, a.y); o.y = pack_h2(a.z, a.w);
        o.z = pack_h2(b.x, b.y); o.w = pack_h2(b.z, b.w);
        ((uint4*)g_W)[v] = o;
    }
}

// ---------------------------------------------------------------------------
// Fused GEMM (mma.sync fp16) + LSTM gating
// ---------------------------------------------------------------------------
__device__ __forceinline__ float fsigmoid(float x) {
    return 1.0f / (1.0f + __expf(-x));
}
__device__ __forceinline__ float ftanh(float x) {
    float e = __expf(2.0f * x);            // inf-safe: 1 - 2/(e+1)
    return 1.0f - 2.0f / (e + 1.0f);
}

// SMEM map: [0,512) bias | [512,536) full mbars x3 | [536,560) empty mbars x3
//           [1024, ...) 3 x 48KB stages
__global__ __launch_bounds__(NTHREADS, 1) void lstm_mma_kernel(
    const float* __restrict__ c_prev,
    const float* __restrict__ bi, const float* __restrict__ bff,
    const float* __restrict__ bo, const float* __restrict__ bc,
    float* __restrict__ out) {
    extern __shared__ char smem[];
    const uint32_t sbase = smem_u32(smem);
    const int tid  = threadIdx.x;
    const int warp = tid >> 5;
    const int lane = tid & 31;

    const int mtile = blockIdx.x & 15;     // 16 M tiles of 256 (fast-varying)
    const int htile = blockIdx.x >> 4;     // 64 H tiles of 32
    const int Mbase = mtile << 8;
    const int Hbase = htile << 5;

    // Bias slice -> SMEM: bs[g*32 + hl], hl in [0,32)
    if (tid < 128) {
        const float* bp = (tid < 32) ? bi : (tid < 64) ? bff : (tid < 96) ? bo : bc;
        ((float*)smem)[tid] = bp[Hbase + (tid & 31)];
    }
    if (tid == 0) {
        #pragma unroll
        for (int s = 0; s < NST; s++) {
            MBARRIER_INIT(sbase + 512 + 8 * s, NTHREADS);   // full (cp.async)
            MBARRIER_INIT(sbase + 536 + 8 * s, NTHREADS);   // empty (readers)
        }
    }

    // ---------------- loader setup (all 256 threads) ----------------
    const int seg = tid & 7;               // 16B segment within 128B row
    const int r0  = tid >> 3;              // 0..31
    const uint32_t swz = (uint32_t)((seg ^ (r0 & 7)) * 16);
    uint32_t aGo[8], bGo[4], aSo[8], bSo[4];
    #pragma unroll
    for (int i = 0; i < 8; i++) {
        const int r = r0 + 32 * i;                       // A tile row 0..255
        aGo[i] = (uint32_t)(Mbase + r) * (DDIM * 2) + (uint32_t)(seg * 16);
        aSo[i] = (uint32_t)(r * 128) + swz;
    }
    #pragma unroll
    for (int i = 0; i < 4; i++) {
        const int n = r0 + 32 * i;                       // B tile row 0..127
        // row order: hblk = n>>6, gate = (n>>4)&3, hl16 = n&15
        const int hblk = n >> 6;
        const int gate = (n >> 4) & 3;
        const int hl16 = n & 15;
        const int grow = gate * HDIM + Hbase + hblk * 16 + hl16;
        bGo[i] = (uint32_t)grow * (DDIM * 2) + (uint32_t)(seg * 16);
        bSo[i] = (uint32_t)(n * 128) + swz + BOFF;
    }
    const char* gA = (const char*)g_A;
    const char* gW = (const char*)g_W;

    // ---------------- mma fragment address setup ----------------
    // warp tile: M rows [(warp&3)*64, +64), B rows [(warp>>2)*64, +64)
    const int aRow   = ((warp & 3) << 6) + (lane & 15);
    const uint32_t aXor  = (uint32_t)(lane & 7);
    const uint32_t aSegH = (uint32_t)(lane >> 4);
    const int bRow   = ((warp >> 2) << 6) + (lane & 7) + ((lane >> 4) << 3);
    const uint32_t bSegH = (uint32_t)((lane >> 3) & 1);

    float acc[4][8][4];
    #pragma unroll
    for (int mi = 0; mi < 4; mi++)
        #pragma unroll
        for (int ni = 0; ni < 8; ni++)
            #pragma unroll
            for (int e = 0; e < 4; e++) acc[mi][ni][e] = 0.0f;

    auto issue = [&](int c, int s) {
        const uint32_t st = sbase + SOFF + (uint32_t)s * STAGE;
        const uint32_t co = (uint32_t)c << 7;   // c * 128 bytes along K
        #pragma unroll
        for (int i = 0; i < 8; i++) CP_ASYNC16(st + aSo[i], gA + aGo[i] + co);
        #pragma unroll
        for (int i = 0; i < 4; i++) CP_ASYNC16(st + bSo[i], gW + bGo[i] + co);
    };

    __syncthreads();    // mbarriers initialized + bias visible

    // Prologue: fill stages 0 and 1.
    issue(0, 0);
    CP_MBARRIER_ARRIVE(sbase + 512 + 0);
    issue(1, 1);
    CP_MBARRIER_ARRIVE(sbase + 512 + 8);

    for (int c = 0; c < NCHUNK; c++) {
        // Produce chunk c+2 into stage (c+2)%3 once its previous readers done.
        const int j = c + 2;
        if (j < NCHUNK) {
            const int sj = j % NST;
            if (j >= NST) MBARRIER_WAIT(sbase + 536 + 8 * sj,
                                        (uint32_t)((j / NST - 1) & 1));
            issue(j, sj);
            CP_MBARRIER_ARRIVE(sbase + 512 + 8 * sj);
        }

        // Consume chunk c.
        const int s = c % NST;
        MBARRIER_WAIT(sbase + 512 + 8 * s, (uint32_t)((c / NST) & 1));

        const uint32_t sA = sbase + SOFF + (uint32_t)s * STAGE;
        const uint32_t sB = sA + BOFF;
        const uint32_t aBase = sA + (uint32_t)(aRow * 128);
        const uint32_t bBase = sB + (uint32_t)(bRow * 128);

        #pragma unroll
        for (int ks = 0; ks < 4; ks++) {
            uint32_t a[4][4];
            const uint32_t aswz = (((uint32_t)(2 * ks) + aSegH) ^ aXor) * 16;
            #pragma unroll
            for (int mi = 0; mi < 4; mi++)
                LDSM_X4(a[mi], aBase + (uint32_t)(mi * 2048) + aswz);
            const uint32_t bswz = (((uint32_t)(2 * ks) + bSegH) ^ aXor) * 16;
            #pragma unroll
            for (int nb = 0; nb < 4; nb++) {      // nb == gate
                uint32_t b[4];
                LDSM_X4(b, bBase + (uint32_t)(nb * 2048) + bswz);
                #pragma unroll
                for (int mi = 0; mi < 4; mi++) {
                    MMA16816(acc[mi][2 * nb],     a[mi], b[0], b[1]);
                    MMA16816(acc[mi][2 * nb + 1], a[mi], b[2], b[3]);
                }
            }
        }

        MBARRIER_ARRIVE(sbase + 536 + 8 * s);   // reader-done for stage s
    }

    // ---------------- fused LSTM epilogue (register-local gating) ----------------
    // acc[mi][2*gate + hc][e]: row = (warp&3)*64 + mi*16 + 8*(e>>1) + lane/4,
    // h col = (warp>>2)*16 + hc*8 + 2*(lane&3) + (e&1)
    const float* bs = (const float*)smem;
    #pragma unroll
    for (int mi = 0; mi < 4; mi++) {
        const int mrow0 = Mbase + ((warp & 3) << 6) + (mi << 4) + (lane >> 2);
        #pragma unroll
        for (int hc = 0; hc < 2; hc++) {
            const int hl = ((warp >> 2) << 4) + (hc << 3) + ((lane & 3) << 1);
            const float bi0 = bs[hl],      bi1 = bs[hl + 1];
            const float bf0 = bs[32 + hl], bf1 = bs[33 + hl];
            const float bo0 = bs[64 + hl], bo1 = bs[65 + hl];
            const float bc0 = bs[96 + hl], bc1 = bs[97 + hl];
            #pragma unroll
            for (int rp = 0; rp < 2; rp++) {
                const int m = mrow0 + (rp << 3);
                const size_t off = (size_t)m * HDIM + (size_t)(Hbase + hl);
                const float2 cp = *(const float2*)(c_prev + off);
                const float zi0 = acc[mi][hc][2 * rp]         + bi0;
                const float zi1 = acc[mi][hc][2 * rp + 1]     + bi1;
                const float zf0 = acc[mi][2 + hc][2 * rp]     + bf0;
                const float zf1 = acc[mi][2 + hc][2 * rp + 1] + bf1;
                const float zo0 = acc[mi][4 + hc][2 * rp]     + bo0;
                const float zo1 = acc[mi][4 + hc][2 * rp + 1] + bo1;
                const float zc0 = acc[mi][6 + hc][2 * rp]     + bc0;
                const float zc1 = acc[mi][6 + hc][2 * rp + 1] + bc1;
                const float ct0 = fsigmoid(zf0) * cp.x + fsigmoid(zi0) * ftanh(zc0);
                const float ct1 = fsigmoid(zf1) * cp.y + fsigmoid(zi1) * ftanh(zc1);
                const float ht0 = fsigmoid(zo0) * ftanh(ct0);
                const float ht1 = fsigmoid(zo1) * ftanh(ct1);
                *(float2*)(out + off) = make_float2(ht0, ht1);
                *(float2*)(out + (size_t)BATCH_N * HDIM + off) = make_float2(ct0, ct1);
            }
        }
    }
}

// ---------------------------------------------------------------------------
// Inputs (metadata order): x_t, h_t_1, c_t_1, W_i, b_i, W_f, b_f, W_o, b_o,
//                          W_c, b_c.  Output: [h_t (B*H), c_t (B*H)] fp32.
// ---------------------------------------------------------------------------
extern "C" void kernel_launch(void* const* d_in, const int* in_sizes, int n_in,
                              void* d_out, int out_size) {
    (void)in_sizes; (void)n_in; (void)out_size;
    const float* x  = (const float*)d_in[0];
    const float* h  = (const float*)d_in[1];
    const float* c  = (const float*)d_in[2];
    const float* Wi = (const float*)d_in[3];
    const float* bi = (const float*)d_in[4];
    const float* Wf = (const float*)d_in[5];
    const float* bf = (const float*)d_in[6];
    const float* Wo = (const float*)d_in[7];
    const float* bo = (const float*)d_in[8];
    const float* Wc = (const float*)d_in[9];
    const float* bc = (const float*)d_in[10];
    float* out = (float*)d_out;

    conv_kernel<<<24576, 256>>>(x, h, Wi, Wf, Wo, Wc);

    cudaFuncSetAttribute(lstm_mma_kernel,
                         cudaFuncAttributeMaxDynamicSharedMemorySize, SMEM_TOTAL);
    lstm_mma_kernel<<<1024, NTHREADS, SMEM_TOTAL>>>(c, bi, bf, bo, bc, out);
}